// round 16
// baseline (speedup 1.0000x reference)
#include <cuda_runtime.h>
#include <cuda_bf16.h>
#include <cstdint>
#include <cstddef>

// Problem dims (fixed by the dataset)
#define M_TOTAL 8192
#define K_DIM   4096
#define N_DIM   16384
#define TILE_M  128
#define TILE_N  128
#define TILE_K  64
#define K_ITERS (K_DIM / TILE_K)   // 64
#define N_TILES (N_DIM / TILE_N)   // 128
#define M_TILES (M_TOTAL / TILE_M) // 64
#define THREADS 256                // 8 warps: 4(M) x 2(N), 32x64 per warp
#define STAGES  3
#define KSLICES (K_DIM / 64)       // 64 norm partials (one per 64-row k slice)
#define JSPLIT  16                 // reduce parallelism over n_tiles

#define A_STAGE (TILE_M * TILE_K * 2)            // 16384 B
#define B_STAGE (TILE_N * TILE_K * 2)            // 16384 B
#define STAGE_BYTES (A_STAGE + B_STAGE)          // 32768
#define SMEM_TOTAL_GEMM (STAGES * STAGE_BYTES)   // 98304 (x2 CTAs = 192K/SM)

#define WT_BLOCKS ((N_DIM / 32) * (K_DIM / 64))  // 32768
#define GB_BLOCKS ((M_TOTAL * K_DIM / 4) / 256)  // 32768

// -------- static device scratch (no allocations allowed) --------
__device__ float          d_norm_part[(size_t)KSLICES * N_DIM];   // per-k-slice col sq-sums
__device__ float          d_norm_inv[N_DIM];
__device__ __nv_bfloat16  d_gb[(size_t)M_TOTAL * K_DIM];          // g in bf16, [M,K] row-major
__device__ __nv_bfloat16  d_wt[(size_t)N_DIM * K_DIM];            // W^T bf16 (UNnormalized), [N,K]
__device__ float          d_partial[(size_t)N_TILES * M_TOTAL];   // partial LSE [n_tile][m]
__device__ float2         d_partial2[(size_t)JSPLIT * M_TOTAL];   // stage-2 (max, sum) pairs

// ------------------------- PTX helpers -------------------------
__device__ __forceinline__ uint32_t smem_u32(const void* p) {
    return (uint32_t)__cvta_generic_to_shared(p);
}
__device__ __forceinline__ void cp_async16(uint32_t smem, const void* gmem) {
    asm volatile("cp.async.cg.shared.global [%0], [%1], 16;" :: "r"(smem), "l"(gmem));
}
__device__ __forceinline__ void cp_commit() {
    asm volatile("cp.async.commit_group;" ::: "memory");
}
__device__ __forceinline__ void cp_wait1() {
    asm volatile("cp.async.wait_group 1;" ::: "memory");
}
__device__ __forceinline__ void ldsm_x4(uint32_t& r0, uint32_t& r1, uint32_t& r2, uint32_t& r3,
                                        uint32_t addr) {
    asm volatile("ldmatrix.sync.aligned.m8n8.x4.shared.b16 {%0,%1,%2,%3}, [%4];"
                 : "=r"(r0), "=r"(r1), "=r"(r2), "=r"(r3) : "r"(addr));
}
__device__ __forceinline__ void mma_bf16(float& d0, float& d1, float& d2, float& d3,
                                         uint32_t a0, uint32_t a1, uint32_t a2, uint32_t a3,
                                         uint32_t b0, uint32_t b1) {
    asm volatile(
        "mma.sync.aligned.m16n8k16.row.col.f32.bf16.bf16.f32 "
        "{%0,%1,%2,%3}, {%4,%5,%6,%7}, {%8,%9}, {%0,%1,%2,%3};"
        : "+f"(d0), "+f"(d1), "+f"(d2), "+f"(d3)
        : "r"(a0), "r"(a1), "r"(a2), "r"(a3), "r"(b0), "r"(b1));
}
__device__ __forceinline__ uint32_t swz(uint32_t byte_off) {
    return byte_off ^ ((byte_off >> 3) & 0x70);
}

// --------------------- merged prep kernel ---------------------
// Blocks [0, WT_BLOCKS): transpose W -> bf16 (unnormalized, 64k x 32h tiles,
// 16B vector stores) + per-64k-slice column sq-sums.
// Blocks [WT_BLOCKS, ...): g -> bf16. Both DRAM-bound; merged to overlap.
__global__ void prep_kernel(const float* __restrict__ W, const float4* __restrict__ g) {
    __shared__ float tile[64][33];     // [k_local][h_local] (wt path only)
    const int b = blockIdx.x;
    const int tid = threadIdx.x;

    if (b < WT_BLOCKS) {
        const int h0 = (b & (N_DIM / 32 - 1)) * 32;
        const int kb = b >> 9;                       // 64-k slice index (N_DIM/32 = 512)
        const int k0 = kb * 64;
        const int tx = tid & 31, ty = tid >> 5;      // (32, 8)
#pragma unroll
        for (int j = 0; j < 64; j += 8)
            tile[ty + j][tx] = W[(size_t)(k0 + ty + j) * N_DIM + h0 + tx];
        __syncthreads();
        // thread -> (h row, 8-k chunk): one 16B store of 8 bf16
        const int hl = tid >> 3;                     // 0..31
        const int kc = tid & 7;                      // 0..7
        const int h = h0 + hl;
        __nv_bfloat162 pk[4];
        float sq = 0.f;
#pragma unroll
        for (int i = 0; i < 4; ++i) {
            float v0 = tile[kc * 8 + i * 2 + 0][hl];
            float v1 = tile[kc * 8 + i * 2 + 1][hl];
            pk[i] = __floats2bfloat162_rn(v0, v1);
            sq = fmaf(v0, v0, sq);
            sq = fmaf(v1, v1, sq);
        }
        *reinterpret_cast<uint4*>(d_wt + (size_t)h * K_DIM + k0 + kc * 8) =
            *reinterpret_cast<uint4*>(pk);
        sq += __shfl_down_sync(0xFFFFFFFF, sq, 4);
        sq += __shfl_down_sync(0xFFFFFFFF, sq, 2);
        sq += __shfl_down_sync(0xFFFFFFFF, sq, 1);
        if (kc == 0)
            d_norm_part[(size_t)kb * N_DIM + h] = sq;
    } else {
        int i = (b - WT_BLOCKS) * 256 + tid;
        float4 v = g[i];
        __nv_bfloat162* o = reinterpret_cast<__nv_bfloat162*>(d_gb) + (size_t)i * 2;
        o[0] = __floats2bfloat162_rn(v.x, v.y);
        o[1] = __floats2bfloat162_rn(v.z, v.w);
    }
}

// finalize: inv = rsqrt(sum of KSLICES partials)
__global__ void norm_finalize_kernel() {
    int h = blockIdx.x * blockDim.x + threadIdx.x;
    float s = 0.f;
#pragma unroll 8
    for (int p = 0; p < KSLICES; ++p) s += d_norm_part[(size_t)p * N_DIM + h];
    d_norm_inv[h] = rsqrtf(s);
}

// --------------------- fused GEMM + partial LSE ---------------------
// 256 threads = 8 warps in 4(M) x 2(N); each warp computes 32x64. 2 CTAs/SM.
// Iteration order: wait -> sync -> { ks-chunk MMA; 2 cp.asyncs for it+2 } x4
// -> commit. The load issue is sliced across the 4 ks chunks so the LSU never
// queues deep enough to delay an ldmatrix or barrier arrival (R15's single
// post-compute burst, smoothed). Slot-reuse guard unchanged.

__global__ void __launch_bounds__(THREADS, 2) gemm_lse_kernel() {
    extern __shared__ char smem[];
    const uint32_t sb = smem_u32(smem);
    const int tid = threadIdx.x;
    const int wid = tid >> 5;
    const int lane = tid & 31;
    const int mw = wid & 3;        // warp M index (0..3)
    const int nw = wid >> 2;       // warp N index (0..1)
    const int m0 = blockIdx.x * TILE_M;    // x = m tile (wave shares B band)
    const int n0 = blockIdx.y * TILE_N;

    const char* aBase = (const char*)d_gb + (size_t)m0 * (K_DIM * 2);
    const char* bBase = (const char*)d_wt + (size_t)n0 * (K_DIM * 2);

    // issue chunks [part*2, part*2+2) of the 8 cp.asyncs for stage s, iter it
    // (ii 0..3 -> A with i=ii; ii 4..7 -> B with i=ii-4 = ii&3)
    auto load_part = [&](int s, int it, int part) {
        const uint32_t ab = sb + s * STAGE_BYTES;
        const char* aK = aBase + it * (TILE_K * 2);
        const char* bK = bBase + it * (TILE_K * 2);
#pragma unroll
        for (int ii = part * 2; ii < part * 2 + 2; ++ii) {
            int idx = tid + (ii & 3) * THREADS;
            uint32_t so = swz((uint32_t)idx * 16);
            if (ii < 4)
                cp_async16(ab + so,
                           aK + (size_t)(idx >> 3) * (K_DIM * 2) + (idx & 7) * 16);
            else
                cp_async16(ab + A_STAGE + so,
                           bK + (size_t)(idx >> 3) * (K_DIM * 2) + (idx & 7) * 16);
        }
    };
    auto load_stage = [&](int s, int it) {
#pragma unroll
        for (int p = 0; p < 4; ++p) load_part(s, it, p);
    };

    load_stage(0, 0); cp_commit();
    load_stage(1, 1); cp_commit();

    float acc[2][8][4];
#pragma unroll
    for (int t = 0; t < 2; ++t)
#pragma unroll
        for (int j = 0; j < 8; ++j)
#pragma unroll
            for (int c = 0; c < 4; ++c) acc[t][j][c] = 0.f;

    // ---- precomputed swizzled LDSM offsets; k-chunk applied via XOR ----
    const int a_row = lane & 15;
    const int a_kh  = lane >> 4;
    const int b_row = lane & 7;
    const int b_grp = (lane >> 3) & 1;
    const int b_t2  = lane >> 4;
    uint32_t a_off[2], b_off[4];
#pragma unroll
    for (int t = 0; t < 2; ++t)
        a_off[t] = swz((uint32_t)(mw * 32 + t * 16 + a_row) * 128 + a_kh * 16);
#pragma unroll
    for (int p = 0; p < 4; ++p)
        b_off[p] = swz((uint32_t)(nw * 64 + p * 16 + b_t2 * 8 + b_row) * 128 + b_grp * 16);

    for (int it = 0; it < K_ITERS; ++it) {
        cp_wait1();                 // stage `it` complete
        __syncthreads();

        const uint32_t stageA = sb + (it % STAGES) * STAGE_BYTES;
        const uint32_t stageB = stageA + A_STAGE;
        const bool doLoad = (it + 2 < K_ITERS);
        const int sNext = (it + 2) % STAGES;

#pragma unroll
        for (int ks = 0; ks < TILE_K / 16; ++ks) {    // 4 k16 steps
            const uint32_t kx = (uint32_t)(ks * 32);
            uint32_t a[2][4];
#pragma unroll
            for (int t = 0; t < 2; ++t)
                ldsm_x4(a[t][0], a[t][1], a[t][2], a[t][3], stageA + (a_off[t] ^ kx));
            uint32_t b[8][2];
#pragma unroll
            for (int p = 0; p < 4; ++p) {
                uint32_t r0, r1, r2, r3;
                ldsm_x4(r0, r1, r2, r3, stageB + (b_off[p] ^ kx));
                b[p * 2][0] = r0; b[p * 2][1] = r1;
                b[p * 2 + 1][0] = r2; b[p * 2 + 1][1] = r3;
            }
#pragma unroll
            for (int t = 0; t < 2; ++t)
#pragma unroll
                for (int j = 0; j < 8; ++j)
                    mma_bf16(acc[t][j][0], acc[t][j][1], acc[t][j][2], acc[t][j][3],
                             a[t][0], a[t][1], a[t][2], a[t][3], b[j][0], b[j][1]);
            if (doLoad) load_part(sNext, it + 2, ks);
        }
        cp_commit();                // one group per iter keeps wait_group uniform
    }

    // ---- apply column normalization to accumulators (fp32) ----
    float ninv[8][2];
#pragma unroll
    for (int j = 0; j < 8; ++j) {
        int n = n0 + nw * 64 + j * 8 + (lane & 3) * 2;
        ninv[j][0] = d_norm_inv[n];
        ninv[j][1] = d_norm_inv[n + 1];
    }
#pragma unroll
    for (int t = 0; t < 2; ++t)
#pragma unroll
        for (int j = 0; j < 8; ++j) {
            acc[t][j][0] *= ninv[j][0];
            acc[t][j][1] *= ninv[j][1];
            acc[t][j][2] *= ninv[j][0];
            acc[t][j][3] *= ninv[j][1];
        }

    __syncthreads();   // all warps done; reuse stage smem for reduction

    // ---- fused epilogue: per-row partial logsumexp over this tile's 128 cols ----
    float2* red = (float2*)smem;   // [2 n-warps][128 rows]
#pragma unroll
    for (int t = 0; t < 2; ++t) {
#pragma unroll
        for (int half = 0; half < 2; ++half) {
            float mx = -3.4e38f;
#pragma unroll
            for (int j = 0; j < 8; ++j) {
                mx = fmaxf(mx, acc[t][j][half * 2]);
                mx = fmaxf(mx, acc[t][j][half * 2 + 1]);
            }
            mx = fmaxf(mx, __shfl_xor_sync(0xFFFFFFFF, mx, 1));
            mx = fmaxf(mx, __shfl_xor_sync(0xFFFFFFFF, mx, 2));
            float s = 0.f;
#pragma unroll
            for (int j = 0; j < 8; ++j) {
                s += __expf(acc[t][j][half * 2] - mx);
                s += __expf(acc[t][j][half * 2 + 1] - mx);
            }
            s += __shfl_xor_sync(0xFFFFFFFF, s, 1);
            s += __shfl_xor_sync(0xFFFFFFFF, s, 2);
            if ((lane & 3) == 0) {
                int row = mw * 32 + t * 16 + half * 8 + (lane >> 2);
                red[nw * 128 + row] = make_float2(mx, s);
            }
        }
    }
    __syncthreads();

    if (tid < TILE_M) {
        float2 v0 = red[tid], v1 = red[128 + tid];
        float m = fmaxf(v0.x, v1.x);
        float s = v0.y * __expf(v0.x - m) + v1.y * __expf(v1.x - m);
        d_partial[(size_t)blockIdx.y * M_TOTAL + m0 + tid] = m + __logf(s);
    }
}

// --------------------- two-stage final LSE combine ---------------------
__global__ void reduce1_kernel() {
    int m = blockIdx.x * blockDim.x + threadIdx.x;
    int js = blockIdx.y;
    int j0 = js * (N_TILES / JSPLIT);
    float mx = -3.4e38f;
#pragma unroll 8
    for (int j = j0; j < j0 + N_TILES / JSPLIT; ++j)
        mx = fmaxf(mx, d_partial[(size_t)j * M_TOTAL + m]);
    float s = 0.f;
#pragma unroll 8
    for (int j = j0; j < j0 + N_TILES / JSPLIT; ++j)
        s += __expf(d_partial[(size_t)j * M_TOTAL + m] - mx);
    d_partial2[(size_t)js * M_TOTAL + m] = make_float2(mx, s);
}

__global__ void reduce2_kernel(float* __restrict__ out) {
    int m = blockIdx.x * blockDim.x + threadIdx.x;
    float mx = -3.4e38f;
#pragma unroll
    for (int p = 0; p < JSPLIT; ++p)
        mx = fmaxf(mx, d_partial2[(size_t)p * M_TOTAL + m].x);
    float s = 0.f;
#pragma unroll
    for (int p = 0; p < JSPLIT; ++p) {
        float2 v = d_partial2[(size_t)p * M_TOTAL + m];
        s += v.y * __expf(v.x - mx);
    }
    out[m] = mx + logf(s);
}

// --------------------- launcher ---------------------
extern "C" void kernel_launch(void* const* d_in, const int* in_sizes, int n_in,
                              void* d_out, int out_size) {
    const float* g;
    const float* W;
    if (in_sizes[0] == M_TOTAL * K_DIM) {           // g first (expected metadata order)
        g = (const float*)d_in[0];
        W = (const float*)d_in[1];
    } else {
        g = (const float*)d_in[1];
        W = (const float*)d_in[0];
    }
    float* out = (float*)d_out;

    prep_kernel<<<WT_BLOCKS + GB_BLOCKS, 256>>>(W, (const float4*)g);
    norm_finalize_kernel<<<N_DIM / 256, 256>>>();

    cudaFuncSetAttribute(gemm_lse_kernel, cudaFuncAttributeMaxDynamicSharedMemorySize,
                         SMEM_TOTAL_GEMM);
    gemm_lse_kernel<<<dim3(M_TILES, N_TILES), THREADS, SMEM_TOTAL_GEMM>>>();

    reduce1_kernel<<<dim3(M_TOTAL / 256, JSPLIT), 256>>>();
    reduce2_kernel<<<M_TOTAL / 256, 256>>>(out);
}